// round 4
// baseline (speedup 1.0000x reference)
#include <cuda_runtime.h>
#include <cuda_fp16.h>
#include <math.h>

// Problem dims (fixed): nx=ny=8192, d=1024, K=512, n_iters=50
#define NX 8192
#define D_DIM 1024
#define KANC 512
#define NITERS 50
#define COLCH 64
#define EPS_INV 20.0f

// ---------------- scratch ----------------------------------------------------
__device__ __align__(16) __half g_K[(size_t)NX * NX];      // exp(cos/eps), 128 MB
__device__ __align__(16) float g_SimX[(size_t)NX * KANC];
__device__ __align__(16) float g_SimY[(size_t)NX * KANC];
__device__ __align__(16) __half g_SXh[(size_t)NX * KANC];  // normalized profile hi
__device__ __align__(16) __half g_SXl[(size_t)NX * KANC];  // normalized profile lo
__device__ __align__(16) __half g_SYh[(size_t)NX * KANC];
__device__ __align__(16) __half g_SYl[(size_t)NX * KANC];
__device__ __align__(16) float g_invX[NX];
__device__ __align__(16) float g_invY[NX];
__device__ __align__(16) float g_invAX[KANC];
__device__ __align__(16) float g_invAY[KANC];
__device__ __align__(16) float g_invSX[NX];
__device__ __align__(16) float g_invSY[NX];
__device__ __align__(16) float g_a[NX];
__device__ __align__(16) float g_b[NX];
__device__ __align__(16) float g_la[NX];
__device__ __align__(16) float g_lb[NX];
__device__ __align__(16) float g_part[(size_t)COLCH * NX];
__device__ int g_cnt[8];   // zero-init; self-resetting finisher counters

// ---------------- f32x2 helpers ----------------------------------------------
__device__ __forceinline__ unsigned long long pack2(float x, float y) {
    unsigned long long r;
    asm("mov.b64 %0, {%1, %2};" : "=l"(r) : "f"(x), "f"(y));
    return r;
}
__device__ __forceinline__ void unpack2(unsigned long long p, float& x, float& y) {
    asm("mov.b64 {%0, %1}, %2;" : "=f"(x), "=f"(y) : "l"(p));
}
__device__ __forceinline__ unsigned long long fma2(unsigned long long a,
                                                   unsigned long long b,
                                                   unsigned long long c) {
    unsigned long long d;
    asm("fma.rn.f32x2 %0, %1, %2, %3;" : "=l"(d) : "l"(a), "l"(b), "l"(c));
    return d;
}

// ---------------- mma helpers ------------------------------------------------
__device__ __forceinline__ unsigned smaddr(const void* p) {
    return (unsigned)__cvta_generic_to_shared(p);
}
__device__ __forceinline__ void ldsm_x4(unsigned addr, unsigned& r0, unsigned& r1,
                                        unsigned& r2, unsigned& r3) {
    asm volatile("ldmatrix.sync.aligned.m8n8.x4.shared.b16 {%0,%1,%2,%3}, [%4];\n"
                 : "=r"(r0), "=r"(r1), "=r"(r2), "=r"(r3) : "r"(addr));
}
__device__ __forceinline__ void mma16816(float* c, const unsigned* a, unsigned b0, unsigned b1) {
    asm volatile("mma.sync.aligned.m16n8k16.row.col.f32.f16.f16.f32 "
                 "{%0,%1,%2,%3},{%4,%5,%6,%7},{%8,%9},{%0,%1,%2,%3};\n"
                 : "+f"(c[0]), "+f"(c[1]), "+f"(c[2]), "+f"(c[3])
                 : "r"(a[0]), "r"(a[1]), "r"(a[2]), "r"(a[3]), "r"(b0), "r"(b1));
}
#define CP16(dst, src) asm volatile("cp.async.cg.shared.global [%0], [%1], 16;\n" ::"r"(dst), "l"(src))
#define CPCOMMIT() asm volatile("cp.async.commit_group;\n")
#define CPWAIT0() asm volatile("cp.async.wait_group 0;\n" ::: "memory")

// ---------------- row L2-norm ------------------------------------------------
__global__ void __launch_bounds__(256) rownorm_kernel(const float* __restrict__ A,
                                                      float* __restrict__ inv, int ncols) {
    int row = blockIdx.x;
    const float4* a4 = (const float4*)(A + (size_t)row * ncols);
    int n4 = ncols >> 2;
    float s = 0.f;
    for (int c = threadIdx.x; c < n4; c += 256) {
        float4 x = a4[c];
        s += x.x * x.x + x.y * x.y + x.z * x.z + x.w * x.w;
    }
#pragma unroll
    for (int o = 16; o; o >>= 1) s += __shfl_xor_sync(0xffffffffu, s, o);
    __shared__ float red[8];
    int lane = threadIdx.x & 31, wid = threadIdx.x >> 5;
    if (lane == 0) red[wid] = s;
    __syncthreads();
    if (threadIdx.x == 0) {
        float t = 0.f;
#pragma unroll
        for (int w = 0; w < 8; w++) t += red[w];
        inv[row] = 1.0f / fmaxf(sqrtf(t), 1e-8f);
    }
}

// ---------------- small NT GEMM (f32x2), float out ---------------------------
#define GBM 128
#define GBN 128
#define GBK 16

__global__ void __launch_bounds__(256) gemm_nt_kernel(const float* __restrict__ A,
                                                      const float* __restrict__ B,
                                                      float* __restrict__ C,
                                                      const float* __restrict__ sa,
                                                      const float* __restrict__ sb,
                                                      int M, int N, int K, float alpha) {
    __shared__ float As[GBK][GBM + 4];
    __shared__ float Bs[GBK][GBN + 4];
    int tid = threadIdx.x;
    int bm = blockIdx.y, bn = blockIdx.x;
    const float* Ab = A + (size_t)bm * GBM * K;
    const float* Bb = B + (size_t)bn * GBN * K;

    int tx = tid & 15;
    int ty = tid >> 4;
    int lr = tid >> 2;
    int lc = (tid & 3) * 4;

    unsigned long long acc[4][8];
#pragma unroll
    for (int ip = 0; ip < 4; ip++)
#pragma unroll
        for (int j = 0; j < 8; j++) acc[ip][j] = 0ULL;

    for (int k0 = 0; k0 < K; k0 += GBK) {
#pragma unroll
        for (int sgm = 0; sgm < 2; sgm++) {
            int r = lr + 64 * sgm;
            float4 a4 = *(const float4*)(Ab + (size_t)r * K + k0 + lc);
            As[lc + 0][r] = a4.x; As[lc + 1][r] = a4.y;
            As[lc + 2][r] = a4.z; As[lc + 3][r] = a4.w;
            float4 b4 = *(const float4*)(Bb + (size_t)r * K + k0 + lc);
            Bs[lc + 0][r] = b4.x; Bs[lc + 1][r] = b4.y;
            Bs[lc + 2][r] = b4.z; Bs[lc + 3][r] = b4.w;
        }
        __syncthreads();
#pragma unroll
        for (int kk = 0; kk < GBK; kk++) {
            float4 a0 = *(const float4*)&As[kk][ty * 4];
            float4 a1 = *(const float4*)&As[kk][ty * 4 + 64];
            float4 b0 = *(const float4*)&Bs[kk][tx * 4];
            float4 b1 = *(const float4*)&Bs[kk][tx * 4 + 64];
            unsigned long long ap[4];
            ap[0] = pack2(a0.x, a0.y); ap[1] = pack2(a0.z, a0.w);
            ap[2] = pack2(a1.x, a1.y); ap[3] = pack2(a1.z, a1.w);
            float bf[8] = {b0.x, b0.y, b0.z, b0.w, b1.x, b1.y, b1.z, b1.w};
            unsigned long long bs2[8];
#pragma unroll
            for (int j = 0; j < 8; j++) bs2[j] = pack2(bf[j], bf[j]);
#pragma unroll
            for (int ip = 0; ip < 4; ip++)
#pragma unroll
                for (int j = 0; j < 8; j++) acc[ip][j] = fma2(ap[ip], bs2[j], acc[ip][j]);
        }
        __syncthreads();
    }

#pragma unroll
    for (int ip = 0; ip < 4; ip++)
#pragma unroll
        for (int h = 0; h < 2; h++) {
            int row = bm * GBM + ty * 4 + ((ip & 1) << 1) + h + ((ip >> 1) << 6);
            float si = sa[row] * alpha;
#pragma unroll
            for (int g = 0; g < 2; g++) {
                int col = bn * GBN + tx * 4 + (g << 6);
                float v[4];
#pragma unroll
                for (int j = 0; j < 4; j++) {
                    float lo, hi;
                    unpack2(acc[ip][g * 4 + j], lo, hi);
                    v[j] = h ? hi : lo;
                }
                float4 o;
                o.x = v[0] * si * sb[col + 0];
                o.y = v[1] * si * sb[col + 1];
                o.z = v[2] * si * sb[col + 2];
                o.w = v[3] * si * sb[col + 3];
                *(float4*)(C + (size_t)row * N + col) = o;
            }
        }
}

// ---------------- split: normalized profile -> fp16 hi + exact lo ------------
__global__ void __launch_bounds__(256) split_kernel(const float* __restrict__ S,
                                                    const float* __restrict__ inv,
                                                    __half* __restrict__ H,
                                                    __half* __restrict__ L) {
    int row = blockIdx.y;
    int c = blockIdx.x * 256 + threadIdx.x;
    float v = S[(size_t)row * KANC + c] * inv[row];
    __half h = __float2half_rn(v);
    float lo = v - __half2float(h);
    H[(size_t)row * KANC + c] = h;
    L[(size_t)row * KANC + c] = __float2half_rn(lo);
}

// ---------------- HMMA split GEMM: K = exp(20 * Ahl . Bhl^T), fp16 out -------
// A,B: [8192][512] fp16 (hi+lo). Tile 128x128x32, 8 warps (warp tile 32x64).
#define MMS 40                       // smem row stride (halves) = 80B, conflict-free
#define MMBUF (128 * MMS)            // halves per matrix per buffer
#define MM_SMEM_BYTES (8 * MMBUF * 2)

__device__ __forceinline__ void mm_prefetch(const __half* gA_h, const __half* gA_l,
                                            const __half* gB_h, const __half* gB_l,
                                            __half* sAh, __half* sAl,
                                            __half* sBh, __half* sBl,
                                            int buf, int k0, int tid) {
#pragma unroll
    for (int s = 0; s < 2; s++) {
        int c = tid + s * 256;
        int row = c >> 2;
        int col = (c & 3) << 3;                 // halves
        size_t go = (size_t)row * KANC + k0 + col;
        int so = buf * MMBUF + row * MMS + col;
        CP16(smaddr(sAh + so), gA_h + go);
        CP16(smaddr(sAl + so), gA_l + go);
        CP16(smaddr(sBh + so), gB_h + go);
        CP16(smaddr(sBl + so), gB_l + go);
    }
}

__global__ void __launch_bounds__(256) hmma_exp_kernel(const __half* __restrict__ Ah,
                                                       const __half* __restrict__ Al,
                                                       const __half* __restrict__ Bh,
                                                       const __half* __restrict__ Bl,
                                                       __half* __restrict__ Kout) {
    extern __shared__ __half smem[];
    __half* sAh = smem;
    __half* sAl = smem + 2 * MMBUF;
    __half* sBh = smem + 4 * MMBUF;
    __half* sBl = smem + 6 * MMBUF;

    int tid = threadIdx.x;
    int bm = blockIdx.y, bn = blockIdx.x;
    const __half* gAh = Ah + (size_t)bm * 128 * KANC;
    const __half* gAl = Al + (size_t)bm * 128 * KANC;
    const __half* gBh = Bh + (size_t)bn * 128 * KANC;
    const __half* gBl = Bl + (size_t)bn * 128 * KANC;

    int wid = tid >> 5, lane = tid & 31;
    int wm = (wid & 3) * 32;     // warp m offset
    int wn = (wid >> 2) * 64;    // warp n offset
    int lrow = lane & 15;
    int lk8 = (lane >> 4) << 3;

    float acc[2][8][4];
#pragma unroll
    for (int mt = 0; mt < 2; mt++)
#pragma unroll
        for (int nt = 0; nt < 8; nt++)
#pragma unroll
            for (int q = 0; q < 4; q++) acc[mt][nt][q] = 0.f;

    mm_prefetch(gAh, gAl, gBh, gBl, sAh, sAl, sBh, sBl, 0, 0, tid);
    CPCOMMIT();
    CPWAIT0();
    __syncthreads();

    const int NITER = KANC / 32;   // 16
    for (int it = 0; it < NITER; it++) {
        int buf = it & 1;
        if (it + 1 < NITER) {
            mm_prefetch(gAh, gAl, gBh, gBl, sAh, sAl, sBh, sBl, buf ^ 1, (it + 1) * 32, tid);
            CPCOMMIT();
        }
#pragma unroll
        for (int k16 = 0; k16 < 2; k16++) {
            int kb = buf * MMBUF + k16 * 16 + lk8;
            unsigned ah[2][4], al[2][4];
#pragma unroll
            for (int mt = 0; mt < 2; mt++) {
                int r = (wm + mt * 16 + lrow) * MMS + kb;
                ldsm_x4(smaddr(sAh + r), ah[mt][0], ah[mt][1], ah[mt][2], ah[mt][3]);
                ldsm_x4(smaddr(sAl + r), al[mt][0], al[mt][1], al[mt][2], al[mt][3]);
            }
            unsigned bh[4][4], bl[4][4];
#pragma unroll
            for (int p = 0; p < 4; p++) {
                int r = (wn + p * 16 + lrow) * MMS + kb;
                ldsm_x4(smaddr(sBh + r), bh[p][0], bh[p][1], bh[p][2], bh[p][3]);
                ldsm_x4(smaddr(sBl + r), bl[p][0], bl[p][1], bl[p][2], bl[p][3]);
            }
#pragma unroll
            for (int mt = 0; mt < 2; mt++)
#pragma unroll
                for (int nt = 0; nt < 8; nt++) {
                    int p = nt >> 1, w = nt & 1;
                    mma16816(acc[mt][nt], ah[mt], bh[p][w], bh[p][w + 2]);
                    mma16816(acc[mt][nt], ah[mt], bl[p][w], bl[p][w + 2]);
                    mma16816(acc[mt][nt], al[mt], bh[p][w], bh[p][w + 2]);
                }
        }
        if (it + 1 < NITER) CPWAIT0();
        __syncthreads();
    }

    // epilogue: *20, exp, half2 stores
    int r0 = lane >> 2;
    int cc = (lane & 3) * 2;
#pragma unroll
    for (int mt = 0; mt < 2; mt++)
#pragma unroll
        for (int nt = 0; nt < 8; nt++) {
            int col = bn * 128 + wn + nt * 8 + cc;
            int rowa = bm * 128 + wm + mt * 16 + r0;
            __half2 h0 = __floats2half2_rn(__expf(acc[mt][nt][0] * EPS_INV),
                                           __expf(acc[mt][nt][1] * EPS_INV));
            __half2 h1 = __floats2half2_rn(__expf(acc[mt][nt][2] * EPS_INV),
                                           __expf(acc[mt][nt][3] * EPS_INV));
            *(__half2*)(Kout + (size_t)rowa * NX + col) = h0;
            *(__half2*)(Kout + (size_t)(rowa + 8) * NX + col) = h1;
        }
}

// ---------------- row matvec: a_i = mu / sum_j K_ij b_j ----------------------
__global__ void __launch_bounds__(256) row_matvec_kernel(const __half* __restrict__ Km,
                                                         const float* __restrict__ b,
                                                         float* __restrict__ a, float mu) {
    int r0 = blockIdx.x * 4;
    const uint4* row0 = (const uint4*)(Km + (size_t)r0 * NX);
    const float4* b4 = (const float4*)b;
    float s0 = 0.f, s1 = 0.f, s2 = 0.f, s3 = 0.f;
#pragma unroll
    for (int it = 0; it < NX / 8 / 256; it++) {
        int c = it * 256 + threadIdx.x;
        float4 bb0 = b4[c * 2], bb1 = b4[c * 2 + 1];
        float bv[8] = {bb0.x, bb0.y, bb0.z, bb0.w, bb1.x, bb1.y, bb1.z, bb1.w};
#pragma unroll
        for (int r = 0; r < 4; r++) {
            uint4 x = row0[c + r * (NX / 8)];
            const __half2* hx = (const __half2*)&x;
            float accv = 0.f;
#pragma unroll
            for (int q = 0; q < 4; q++) {
                float2 f = __half22float2(hx[q]);
                accv += f.x * bv[q * 2] + f.y * bv[q * 2 + 1];
            }
            if (r == 0) s0 += accv;
            else if (r == 1) s1 += accv;
            else if (r == 2) s2 += accv;
            else s3 += accv;
        }
    }
#pragma unroll
    for (int o = 16; o; o >>= 1) {
        s0 += __shfl_xor_sync(0xffffffffu, s0, o);
        s1 += __shfl_xor_sync(0xffffffffu, s1, o);
        s2 += __shfl_xor_sync(0xffffffffu, s2, o);
        s3 += __shfl_xor_sync(0xffffffffu, s3, o);
    }
    __shared__ float red[8][4];
    int lane = threadIdx.x & 31, wid = threadIdx.x >> 5;
    if (lane == 0) { red[wid][0] = s0; red[wid][1] = s1; red[wid][2] = s2; red[wid][3] = s3; }
    __syncthreads();
    if (threadIdx.x < 4) {
        float t = 0.f;
#pragma unroll
        for (int w = 0; w < 8; w++) t += red[w][threadIdx.x];
        a[r0 + threadIdx.x] = mu / t;
    }
}

// ---------------- col matvec, fused combine (last-block pattern) -------------
__global__ void __launch_bounds__(256) col_partial_kernel(const __half* __restrict__ Km,
                                                          const float* __restrict__ a,
                                                          float* __restrict__ part,
                                                          float* __restrict__ b, float nu) {
    int j8 = blockIdx.x * 256 + threadIdx.x;
    int r0 = blockIdx.y * (NX / COLCH);
    const uint4* base = (const uint4*)Km + (size_t)r0 * (NX / 8) + j8;
    float s[8];
#pragma unroll
    for (int q = 0; q < 8; q++) s[q] = 0.f;
#pragma unroll 4
    for (int r = 0; r < NX / COLCH; r++) {
        uint4 x = base[(size_t)r * (NX / 8)];
        float av = __ldg(&a[r0 + r]);
        const __half2* hx = (const __half2*)&x;
#pragma unroll
        for (int q = 0; q < 4; q++) {
            float2 f = __half22float2(hx[q]);
            s[q * 2] += f.x * av;
            s[q * 2 + 1] += f.y * av;
        }
    }
    size_t o = (size_t)blockIdx.y * NX + (size_t)j8 * 8;
    *(float4*)(part + o) = make_float4(s[0], s[1], s[2], s[3]);
    *(float4*)(part + o + 4) = make_float4(s[4], s[5], s[6], s[7]);

    // last-block-per-column-group combines
    __threadfence();
    __syncthreads();
    __shared__ int isLast;
    if (threadIdx.x == 0) {
        int old = atomicAdd(&g_cnt[blockIdx.x], 1);
        isLast = (old == COLCH - 1);
        if (isLast) g_cnt[blockIdx.x] = 0;   // reset for next launch / replay
    }
    __syncthreads();
    if (isLast) {
        __threadfence();
#pragma unroll
        for (int q = 0; q < 8; q++) {
            int j = blockIdx.x * 2048 + q * 256 + threadIdx.x;
            float t = 0.f;
#pragma unroll 8
            for (int c = 0; c < COLCH; c++) t += part[(size_t)c * NX + j];
            b[j] = nu / t;
        }
    }
}

// ---------------- misc -------------------------------------------------------
__global__ void __launch_bounds__(256) ones_kernel(float* __restrict__ p) {
    p[blockIdx.x * 256 + threadIdx.x] = 1.0f;
}

__global__ void __launch_bounds__(256) log_kernel(const float* __restrict__ a,
                                                  const float* __restrict__ b,
                                                  float* __restrict__ la,
                                                  float* __restrict__ lb) {
    int i = blockIdx.x * 256 + threadIdx.x;
    la[i] = __logf(a[i]);
    lb[i] = __logf(b[i]);
}

__global__ void __launch_bounds__(256) epilogue_kernel(const __half* __restrict__ Km,
                                                       const float* __restrict__ a,
                                                       const float* __restrict__ b,
                                                       const float* __restrict__ la,
                                                       const float* __restrict__ lb,
                                                       float* __restrict__ plan,
                                                       float* __restrict__ logplan) {
    int row = blockIdx.y;
    int c8 = blockIdx.x * 256 + threadIdx.x;
    size_t kidx = (size_t)row * (NX / 8) + c8;
    uint4 x = ((const uint4*)Km)[kidx];
    const __half2* hx = (const __half2*)&x;
    float av = a[row];
    float ul = la[row];
    float kf[8];
#pragma unroll
    for (int q = 0; q < 4; q++) {
        float2 f = __half22float2(hx[q]);
        kf[q * 2] = f.x; kf[q * 2 + 1] = f.y;
    }
    float4 bb0 = ((const float4*)b)[c8 * 2];
    float4 bb1 = ((const float4*)b)[c8 * 2 + 1];
    float4 lv0 = ((const float4*)lb)[c8 * 2];
    float4 lv1 = ((const float4*)lb)[c8 * 2 + 1];
    float bv[8] = {bb0.x, bb0.y, bb0.z, bb0.w, bb1.x, bb1.y, bb1.z, bb1.w};
    float lvv[8] = {lv0.x, lv0.y, lv0.z, lv0.w, lv1.x, lv1.y, lv1.z, lv1.w};
    float p[8], lp[8];
#pragma unroll
    for (int q = 0; q < 8; q++) {
        p[q] = (kf[q] * av) * bv[q];
        lp[q] = __logf(kf[q]) + ul + lvv[q];
    }
    size_t o4 = (size_t)row * (NX / 4) + (size_t)c8 * 2;
    ((float4*)plan)[o4] = make_float4(p[0], p[1], p[2], p[3]);
    ((float4*)plan)[o4 + 1] = make_float4(p[4], p[5], p[6], p[7]);
    ((float4*)logplan)[o4] = make_float4(lp[0], lp[1], lp[2], lp[3]);
    ((float4*)logplan)[o4 + 1] = make_float4(lp[4], lp[5], lp[6], lp[7]);
}

// ---------------- launch -----------------------------------------------------
extern "C" void kernel_launch(void* const* d_in, const int* in_sizes, int n_in,
                              void* d_out, int out_size) {
    const float* X  = (const float*)d_in[0];
    const float* Y  = (const float*)d_in[1];
    const float* aX = (const float*)d_in[2];
    const float* aY = (const float*)d_in[3];
    float* out = (float*)d_out;

    __half *pK, *pSXh, *pSXl, *pSYh, *pSYl;
    float *pSX, *pSY, *pinvX, *pinvY, *pinvAX, *pinvAY, *pinvSX, *pinvSY;
    float *pa, *pb, *pla, *plb, *ppart;
    cudaGetSymbolAddress((void**)&pK, g_K);
    cudaGetSymbolAddress((void**)&pSX, g_SimX);
    cudaGetSymbolAddress((void**)&pSY, g_SimY);
    cudaGetSymbolAddress((void**)&pSXh, g_SXh);
    cudaGetSymbolAddress((void**)&pSXl, g_SXl);
    cudaGetSymbolAddress((void**)&pSYh, g_SYh);
    cudaGetSymbolAddress((void**)&pSYl, g_SYl);
    cudaGetSymbolAddress((void**)&pinvX, g_invX);
    cudaGetSymbolAddress((void**)&pinvY, g_invY);
    cudaGetSymbolAddress((void**)&pinvAX, g_invAX);
    cudaGetSymbolAddress((void**)&pinvAY, g_invAY);
    cudaGetSymbolAddress((void**)&pinvSX, g_invSX);
    cudaGetSymbolAddress((void**)&pinvSY, g_invSY);
    cudaGetSymbolAddress((void**)&pa, g_a);
    cudaGetSymbolAddress((void**)&pb, g_b);
    cudaGetSymbolAddress((void**)&pla, g_la);
    cudaGetSymbolAddress((void**)&plb, g_lb);
    cudaGetSymbolAddress((void**)&ppart, g_part);

    cudaFuncSetAttribute(hmma_exp_kernel, cudaFuncAttributeMaxDynamicSharedMemorySize,
                         MM_SMEM_BYTES);

    const float MU = 1.0f / 8192.0f;

    // 1) inverse row norms
    rownorm_kernel<<<NX, 256>>>(X, pinvX, D_DIM);
    rownorm_kernel<<<NX, 256>>>(Y, pinvY, D_DIM);
    rownorm_kernel<<<KANC, 256>>>(aX, pinvAX, D_DIM);
    rownorm_kernel<<<KANC, 256>>>(aY, pinvAY, D_DIM);

    // 2) similarity profiles (f32x2 FFMA GEMM)
    gemm_nt_kernel<<<dim3(KANC / GBN, NX / GBM), 256>>>(X, aX, pSX, pinvX, pinvAX,
                                                        NX, KANC, D_DIM, 1.0f);
    gemm_nt_kernel<<<dim3(KANC / GBN, NX / GBM), 256>>>(Y, aY, pSY, pinvY, pinvAY,
                                                        NX, KANC, D_DIM, 1.0f);

    // 3) profile inverse norms + normalized fp16 hi/lo split
    rownorm_kernel<<<NX, 256>>>(pSX, pinvSX, KANC);
    rownorm_kernel<<<NX, 256>>>(pSY, pinvSY, KANC);
    split_kernel<<<dim3(KANC / 256, NX), 256>>>(pSX, pinvSX, pSXh, pSXl);
    split_kernel<<<dim3(KANC / 256, NX), 256>>>(pSY, pinvSY, pSYh, pSYl);

    // 4) K = exp(20 * cos), fp16, via split-HMMA
    hmma_exp_kernel<<<dim3(NX / 128, NX / 128), 256, MM_SMEM_BYTES>>>(pSXh, pSXl,
                                                                      pSYh, pSYl, pK);

    // 5) sinkhorn, exp domain
    ones_kernel<<<NX / 256, 256>>>(pb);
    for (int it = 0; it < NITERS; it++) {
        row_matvec_kernel<<<NX / 4, 256>>>(pK, pb, pa, MU);
        col_partial_kernel<<<dim3(NX / (256 * 8), COLCH), 256>>>(pK, pa, ppart, pb, MU);
    }
    log_kernel<<<NX / 256, 256>>>(pa, pb, pla, plb);

    // 6) outputs
    epilogue_kernel<<<dim3(NX / (256 * 8), NX), 256>>>(pK, pa, pb, pla, plb,
                                                       out, out + (size_t)NX * NX);
}

// round 6
// speedup vs baseline: 1.1035x; 1.1035x over previous
#include <cuda_runtime.h>
#include <cuda_fp16.h>
#include <cstdint>
#include <math.h>

// Problem dims (fixed): nx=ny=8192, d=1024, K=512, n_iters=50
#define NX 8192
#define D_DIM 1024
#define KANC 512
#define NITERS 50
#define COLCH 64
#define EPS_INV 20.0f
#define PERSIST_ROWS 6656           // 104 MB of K kept L2-resident (evict_last)

// ---------------- scratch ----------------------------------------------------
__device__ __align__(16) __half g_K[(size_t)NX * NX];      // exp(cos/eps), 128 MB
__device__ __align__(16) float g_SimX[(size_t)NX * KANC];
__device__ __align__(16) float g_SimY[(size_t)NX * KANC];
__device__ __align__(16) float g_invX[NX];
__device__ __align__(16) float g_invY[NX];
__device__ __align__(16) float g_invAX[KANC];
__device__ __align__(16) float g_invAY[KANC];
__device__ __align__(16) float g_invSX[NX];
__device__ __align__(16) float g_invSY[NX];
__device__ __align__(16) float g_a[NX];
__device__ __align__(16) float g_b[NX];
__device__ __align__(16) float g_la[NX];
__device__ __align__(16) float g_lb[NX];
__device__ __align__(16) float g_part[(size_t)COLCH * NX];

// ---------------- f32x2 helpers ----------------------------------------------
__device__ __forceinline__ unsigned long long pack2(float x, float y) {
    unsigned long long r;
    asm("mov.b64 %0, {%1, %2};" : "=l"(r) : "f"(x), "f"(y));
    return r;
}
__device__ __forceinline__ void unpack2(unsigned long long p, float& x, float& y) {
    asm("mov.b64 {%0, %1}, %2;" : "=f"(x), "=f"(y) : "l"(p));
}
__device__ __forceinline__ unsigned long long fma2(unsigned long long a,
                                                   unsigned long long b,
                                                   unsigned long long c) {
    unsigned long long d;
    asm("fma.rn.f32x2 %0, %1, %2, %3;" : "=l"(d) : "l"(a), "l"(b), "l"(c));
    return d;
}

// ---------------- L2 cache-policy helpers ------------------------------------
__device__ __forceinline__ unsigned long long pol_keep() {
    unsigned long long p;
    asm("createpolicy.fractional.L2::evict_last.b64 %0, 1.0;" : "=l"(p));
    return p;
}
__device__ __forceinline__ unsigned long long pol_stream() {
    unsigned long long p;
    asm("createpolicy.fractional.L2::evict_first.b64 %0, 1.0;" : "=l"(p));
    return p;
}
__device__ __forceinline__ uint4 ldg4_hint(const uint4* p, unsigned long long pol) {
    uint4 r;
    asm volatile("ld.global.nc.L2::cache_hint.v4.u32 {%0,%1,%2,%3}, [%4], %5;"
                 : "=r"(r.x), "=r"(r.y), "=r"(r.z), "=r"(r.w) : "l"(p), "l"(pol));
    return r;
}
__device__ __forceinline__ void stg2_hint(void* p, uint2 v, unsigned long long pol) {
    asm volatile("st.global.L2::cache_hint.v2.u32 [%0], {%1,%2}, %3;"
                 :: "l"(p), "r"(v.x), "r"(v.y), "l"(pol) : "memory");
}
__device__ __forceinline__ void stg4_hint(void* p, float4 v, unsigned long long pol) {
    asm volatile("st.global.L2::cache_hint.v4.f32 [%0], {%1,%2,%3,%4}, %5;"
                 :: "l"(p), "f"(v.x), "f"(v.y), "f"(v.z), "f"(v.w), "l"(pol) : "memory");
}

// ---------------- row L2-norm ------------------------------------------------
__global__ void __launch_bounds__(256) rownorm_kernel(const float* __restrict__ A,
                                                      float* __restrict__ inv, int ncols) {
    int row = blockIdx.x;
    const float4* a4 = (const float4*)(A + (size_t)row * ncols);
    int n4 = ncols >> 2;
    float s = 0.f;
    for (int c = threadIdx.x; c < n4; c += 256) {
        float4 x = a4[c];
        s += x.x * x.x + x.y * x.y + x.z * x.z + x.w * x.w;
    }
#pragma unroll
    for (int o = 16; o; o >>= 1) s += __shfl_xor_sync(0xffffffffu, s, o);
    __shared__ float red[8];
    int lane = threadIdx.x & 31, wid = threadIdx.x >> 5;
    if (lane == 0) red[wid] = s;
    __syncthreads();
    if (threadIdx.x == 0) {
        float t = 0.f;
#pragma unroll
        for (int w = 0; w < 8; w++) t += red[w];
        inv[row] = 1.0f / fmaxf(sqrtf(t), 1e-8f);
    }
}

// ---------------- NT GEMM (f32x2); fp32 out or exp->fp16 out -----------------
#define GBM 128
#define GBN 128
#define GBK 16

__global__ void __launch_bounds__(256) gemm_nt_kernel(const float* __restrict__ A,
                                                      const float* __restrict__ B,
                                                      float* __restrict__ C,
                                                      __half* __restrict__ Ch,
                                                      const float* __restrict__ sa,
                                                      const float* __restrict__ sb,
                                                      int M, int N, int K, float alpha,
                                                      int do_exp) {
    __shared__ float As[GBK][GBM + 4];
    __shared__ float Bs[GBK][GBN + 4];
    int tid = threadIdx.x;
    int bm = blockIdx.y, bn = blockIdx.x;
    const float* Ab = A + (size_t)bm * GBM * K;
    const float* Bb = B + (size_t)bn * GBN * K;

    int tx = tid & 15;
    int ty = tid >> 4;
    int lr = tid >> 2;
    int lc = (tid & 3) * 4;

    unsigned long long acc[4][8];
#pragma unroll
    for (int ip = 0; ip < 4; ip++)
#pragma unroll
        for (int j = 0; j < 8; j++) acc[ip][j] = 0ULL;

    for (int k0 = 0; k0 < K; k0 += GBK) {
#pragma unroll
        for (int sgm = 0; sgm < 2; sgm++) {
            int r = lr + 64 * sgm;
            float4 a4 = *(const float4*)(Ab + (size_t)r * K + k0 + lc);
            As[lc + 0][r] = a4.x; As[lc + 1][r] = a4.y;
            As[lc + 2][r] = a4.z; As[lc + 3][r] = a4.w;
            float4 b4 = *(const float4*)(Bb + (size_t)r * K + k0 + lc);
            Bs[lc + 0][r] = b4.x; Bs[lc + 1][r] = b4.y;
            Bs[lc + 2][r] = b4.z; Bs[lc + 3][r] = b4.w;
        }
        __syncthreads();
#pragma unroll
        for (int kk = 0; kk < GBK; kk++) {
            float4 a0 = *(const float4*)&As[kk][ty * 4];
            float4 a1 = *(const float4*)&As[kk][ty * 4 + 64];
            float4 b0 = *(const float4*)&Bs[kk][tx * 4];
            float4 b1 = *(const float4*)&Bs[kk][tx * 4 + 64];
            unsigned long long ap[4];
            ap[0] = pack2(a0.x, a0.y); ap[1] = pack2(a0.z, a0.w);
            ap[2] = pack2(a1.x, a1.y); ap[3] = pack2(a1.z, a1.w);
            float bf[8] = {b0.x, b0.y, b0.z, b0.w, b1.x, b1.y, b1.z, b1.w};
            unsigned long long bs2[8];
#pragma unroll
            for (int j = 0; j < 8; j++) bs2[j] = pack2(bf[j], bf[j]);
#pragma unroll
            for (int ip = 0; ip < 4; ip++)
#pragma unroll
                for (int j = 0; j < 8; j++) acc[ip][j] = fma2(ap[ip], bs2[j], acc[ip][j]);
        }
        __syncthreads();
    }

    unsigned long long pk = pol_keep(), ps = pol_stream();
#pragma unroll
    for (int ip = 0; ip < 4; ip++)
#pragma unroll
        for (int h = 0; h < 2; h++) {
            int row = bm * GBM + ty * 4 + ((ip & 1) << 1) + h + ((ip >> 1) << 6);
            float si = sa[row] * alpha;
#pragma unroll
            for (int g = 0; g < 2; g++) {
                int col = bn * GBN + tx * 4 + (g << 6);
                float v[4];
#pragma unroll
                for (int j = 0; j < 4; j++) {
                    float lo, hi;
                    unpack2(acc[ip][g * 4 + j], lo, hi);
                    v[j] = h ? hi : lo;
                }
                float4 o;
                o.x = v[0] * si * sb[col + 0];
                o.y = v[1] * si * sb[col + 1];
                o.z = v[2] * si * sb[col + 2];
                o.w = v[3] * si * sb[col + 3];
                if (do_exp) {
                    __half2 h0 = __floats2half2_rn(__expf(o.x), __expf(o.y));
                    __half2 h1 = __floats2half2_rn(__expf(o.z), __expf(o.w));
                    uint2 pkv;
                    pkv.x = *(unsigned int*)&h0;
                    pkv.y = *(unsigned int*)&h1;
                    stg2_hint(Ch + (size_t)row * N + col, pkv,
                              row < PERSIST_ROWS ? pk : ps);
                } else {
                    *(float4*)(C + (size_t)row * N + col) = o;
                }
            }
        }
}

// ---------------- row matvec: a_i = mu / sum_j K_ij b_j ----------------------
__global__ void __launch_bounds__(256) row_matvec_kernel(const __half* __restrict__ Km,
                                                         const float* __restrict__ b,
                                                         float* __restrict__ a, float mu) {
    int r0 = blockIdx.x * 4;
    const uint4* row0 = (const uint4*)(Km + (size_t)r0 * NX);
    const float4* b4 = (const float4*)b;
    unsigned long long pol = (r0 < PERSIST_ROWS) ? pol_keep() : pol_stream();
    float s0 = 0.f, s1 = 0.f, s2 = 0.f, s3 = 0.f;
#pragma unroll
    for (int it = 0; it < NX / 8 / 256; it++) {
        int c = it * 256 + threadIdx.x;
        float4 bb0 = b4[c * 2], bb1 = b4[c * 2 + 1];
        float bv[8] = {bb0.x, bb0.y, bb0.z, bb0.w, bb1.x, bb1.y, bb1.z, bb1.w};
#pragma unroll
        for (int r = 0; r < 4; r++) {
            uint4 x = ldg4_hint(row0 + c + r * (NX / 8), pol);
            const __half2* hx = (const __half2*)&x;
            float accv = 0.f;
#pragma unroll
            for (int q = 0; q < 4; q++) {
                float2 f = __half22float2(hx[q]);
                accv += f.x * bv[q * 2] + f.y * bv[q * 2 + 1];
            }
            if (r == 0) s0 += accv;
            else if (r == 1) s1 += accv;
            else if (r == 2) s2 += accv;
            else s3 += accv;
        }
    }
#pragma unroll
    for (int o = 16; o; o >>= 1) {
        s0 += __shfl_xor_sync(0xffffffffu, s0, o);
        s1 += __shfl_xor_sync(0xffffffffu, s1, o);
        s2 += __shfl_xor_sync(0xffffffffu, s2, o);
        s3 += __shfl_xor_sync(0xffffffffu, s3, o);
    }
    __shared__ float red[8][4];
    int lane = threadIdx.x & 31, wid = threadIdx.x >> 5;
    if (lane == 0) { red[wid][0] = s0; red[wid][1] = s1; red[wid][2] = s2; red[wid][3] = s3; }
    __syncthreads();
    if (threadIdx.x < 4) {
        float t = 0.f;
#pragma unroll
        for (int w = 0; w < 8; w++) t += red[w][threadIdx.x];
        a[r0 + threadIdx.x] = mu / t;
    }
}

// ---------------- col matvec (2-stage): b_j = nu / sum_i K_ij a_i ------------
__global__ void __launch_bounds__(256) col_partial_kernel(const __half* __restrict__ Km,
                                                          const float* __restrict__ a,
                                                          float* __restrict__ part) {
    int j8 = blockIdx.x * 256 + threadIdx.x;
    int r0 = blockIdx.y * (NX / COLCH);
    const uint4* base = (const uint4*)Km + (size_t)r0 * (NX / 8) + j8;
    unsigned long long pol = (r0 < PERSIST_ROWS) ? pol_keep() : pol_stream();
    float s[8];
#pragma unroll
    for (int q = 0; q < 8; q++) s[q] = 0.f;
#pragma unroll 4
    for (int r = 0; r < NX / COLCH; r++) {
        uint4 x = ldg4_hint(base + (size_t)r * (NX / 8), pol);
        float av = __ldg(&a[r0 + r]);
        const __half2* hx = (const __half2*)&x;
#pragma unroll
        for (int q = 0; q < 4; q++) {
            float2 f = __half22float2(hx[q]);
            s[q * 2] += f.x * av;
            s[q * 2 + 1] += f.y * av;
        }
    }
    size_t o = (size_t)blockIdx.y * NX + (size_t)j8 * 8;
    *(float4*)(part + o) = make_float4(s[0], s[1], s[2], s[3]);
    *(float4*)(part + o + 4) = make_float4(s[4], s[5], s[6], s[7]);
}

__global__ void __launch_bounds__(256) col_combine_kernel(const float* __restrict__ part,
                                                          float* __restrict__ b, float nu) {
    int j = blockIdx.x * 256 + threadIdx.x;
    float t = 0.f;
#pragma unroll 8
    for (int c = 0; c < COLCH; c++) t += part[(size_t)c * NX + j];
    b[j] = nu / t;
}

// ---------------- misc -------------------------------------------------------
__global__ void __launch_bounds__(256) ones_kernel(float* __restrict__ p) {
    p[blockIdx.x * 256 + threadIdx.x] = 1.0f;
}

__global__ void __launch_bounds__(256) log_kernel(const float* __restrict__ a,
                                                  const float* __restrict__ b,
                                                  float* __restrict__ la,
                                                  float* __restrict__ lb) {
    int i = blockIdx.x * 256 + threadIdx.x;
    la[i] = __logf(a[i]);
    lb[i] = __logf(b[i]);
}

__global__ void __launch_bounds__(256) epilogue_kernel(const __half* __restrict__ Km,
                                                       const float* __restrict__ a,
                                                       const float* __restrict__ b,
                                                       const float* __restrict__ la,
                                                       const float* __restrict__ lb,
                                                       float* __restrict__ plan,
                                                       float* __restrict__ logplan) {
    int row = blockIdx.y;
    int c8 = blockIdx.x * 256 + threadIdx.x;
    size_t kidx = (size_t)row * (NX / 8) + c8;
    unsigned long long pk = (row < PERSIST_ROWS) ? pol_keep() : pol_stream();
    unsigned long long ps = pol_stream();
    uint4 x = ldg4_hint((const uint4*)Km + kidx, pk);
    const __half2* hx = (const __half2*)&x;
    float av = a[row];
    float ul = la[row];
    float kf[8];
#pragma unroll
    for (int q = 0; q < 4; q++) {
        float2 f = __half22float2(hx[q]);
        kf[q * 2] = f.x; kf[q * 2 + 1] = f.y;
    }
    float4 bb0 = ((const float4*)b)[c8 * 2];
    float4 bb1 = ((const float4*)b)[c8 * 2 + 1];
    float4 lv0 = ((const float4*)lb)[c8 * 2];
    float4 lv1 = ((const float4*)lb)[c8 * 2 + 1];
    float bv[8] = {bb0.x, bb0.y, bb0.z, bb0.w, bb1.x, bb1.y, bb1.z, bb1.w};
    float lvv[8] = {lv0.x, lv0.y, lv0.z, lv0.w, lv1.x, lv1.y, lv1.z, lv1.w};
    float p[8], lp[8];
#pragma unroll
    for (int q = 0; q < 8; q++) {
        p[q] = (kf[q] * av) * bv[q];
        lp[q] = __logf(kf[q]) + ul + lvv[q];
    }
    size_t o4 = (size_t)row * (NX / 4) + (size_t)c8 * 2;
    stg4_hint(plan + o4 * 4, make_float4(p[0], p[1], p[2], p[3]), ps);
    stg4_hint(plan + o4 * 4 + 4, make_float4(p[4], p[5], p[6], p[7]), ps);
    stg4_hint(logplan + o4 * 4, make_float4(lp[0], lp[1], lp[2], lp[3]), ps);
    stg4_hint(logplan + o4 * 4 + 4, make_float4(lp[4], lp[5], lp[6], lp[7]), ps);
}

// ---------------- launch -----------------------------------------------------
extern "C" void kernel_launch(void* const* d_in, const int* in_sizes, int n_in,
                              void* d_out, int out_size) {
    const float* X  = (const float*)d_in[0];
    const float* Y  = (const float*)d_in[1];
    const float* aX = (const float*)d_in[2];
    const float* aY = (const float*)d_in[3];
    float* out = (float*)d_out;

    __half* pK;
    float *pSX, *pSY, *pinvX, *pinvY, *pinvAX, *pinvAY, *pinvSX, *pinvSY;
    float *pa, *pb, *pla, *plb, *ppart;
    cudaGetSymbolAddress((void**)&pK, g_K);
    cudaGetSymbolAddress((void**)&pSX, g_SimX);
    cudaGetSymbolAddress((void**)&pSY, g_SimY);
    cudaGetSymbolAddress((void**)&pinvX, g_invX);
    cudaGetSymbolAddress((void**)&pinvY, g_invY);
    cudaGetSymbolAddress((void**)&pinvAX, g_invAX);
    cudaGetSymbolAddress((void**)&pinvAY, g_invAY);
    cudaGetSymbolAddress((void**)&pinvSX, g_invSX);
    cudaGetSymbolAddress((void**)&pinvSY, g_invSY);
    cudaGetSymbolAddress((void**)&pa, g_a);
    cudaGetSymbolAddress((void**)&pb, g_b);
    cudaGetSymbolAddress((void**)&pla, g_la);
    cudaGetSymbolAddress((void**)&plb, g_lb);
    cudaGetSymbolAddress((void**)&ppart, g_part);

    const float MU = 1.0f / 8192.0f;

    // 1) inverse row norms
    rownorm_kernel<<<NX, 256>>>(X, pinvX, D_DIM);
    rownorm_kernel<<<NX, 256>>>(Y, pinvY, D_DIM);
    rownorm_kernel<<<KANC, 256>>>(aX, pinvAX, D_DIM);
    rownorm_kernel<<<KANC, 256>>>(aY, pinvAY, D_DIM);

    // 2) similarity profiles (f32x2 FFMA GEMM)
    gemm_nt_kernel<<<dim3(KANC / GBN, NX / GBM), 256>>>(X, aX, pSX, (__half*)0, pinvX, pinvAX,
                                                        NX, KANC, D_DIM, 1.0f, 0);
    gemm_nt_kernel<<<dim3(KANC / GBN, NX / GBM), 256>>>(Y, aY, pSY, (__half*)0, pinvY, pinvAY,
                                                        NX, KANC, D_DIM, 1.0f, 0);

    // 3) profile inverse norms
    rownorm_kernel<<<NX, 256>>>(pSX, pinvSX, KANC);
    rownorm_kernel<<<NX, 256>>>(pSY, pinvSY, KANC);

    // 4) K = exp(cos/eps), fp16, persist region tagged evict_last
    gemm_nt_kernel<<<dim3(NX / GBN, NX / GBM), 256>>>(pSX, pSY, (float*)0, pK, pinvSX, pinvSY,
                                                      NX, NX, KANC, EPS_INV, 1);

    // 5) sinkhorn, exp domain
    ones_kernel<<<NX / 256, 256>>>(pb);
    for (int it = 0; it < NITERS; it++) {
        row_matvec_kernel<<<NX / 4, 256>>>(pK, pb, pa, MU);
        col_partial_kernel<<<dim3(NX / (256 * 8), COLCH), 256>>>(pK, pa, ppart);
        col_combine_kernel<<<NX / 256, 256>>>(ppart, pb, MU);
    }
    log_kernel<<<NX / 256, 256>>>(pa, pb, pla, plb);

    // 6) outputs
    epilogue_kernel<<<dim3(NX / (256 * 8), NX), 256>>>(pK, pa, pb, pla, plb,
                                                       out, out + (size_t)NX * NX);
}